// round 7
// baseline (speedup 1.0000x reference)
#include <cuda_runtime.h>
#include <cuda_bf16.h>
#include <math.h>
#include <stdint.h>

#define EMBED 1024
#define NH 16
#define DK 64
#define BATCH 2
#define SEQ 2048
#define M_ROWS (BATCH*SEQ)      // 4096
#define QKV_COLS (3*EMBED)      // 3072

// log2(e) / sqrt(1024) — folded into Q at the QKV epilogue
#define QSCALE 0.0450842200f

// ---------------- scratch (__device__ globals) ------------------------------
__device__ __align__(16) __nv_bfloat16 g_x_hi[M_ROWS*EMBED];
__device__ __align__(16) __nv_bfloat16 g_x_lo[M_ROWS*EMBED];
__device__ __align__(16) __nv_bfloat16 g_wqkv_hi[QKV_COLS*EMBED];
__device__ __align__(16) __nv_bfloat16 g_wqkv_lo[QKV_COLS*EMBED];
__device__ __align__(16) __nv_bfloat16 g_wo_hi[EMBED*EMBED];
__device__ __align__(16) __nv_bfloat16 g_wo_lo[EMBED*EMBED];

__device__ __align__(16) __nv_bfloat16 g_q_hi[BATCH*NH*SEQ*DK];  // [B,H,N,dk] (pre-scaled)
__device__ __align__(16) __nv_bfloat16 g_q_lo[BATCH*NH*SEQ*DK];
__device__ __align__(16) __nv_bfloat16 g_k_hi[BATCH*NH*SEQ*DK];  // [B,H,N,dk]
__device__ __align__(16) __nv_bfloat16 g_k_lo[BATCH*NH*SEQ*DK];
__device__ __align__(16) __nv_bfloat16 g_vt_hi[BATCH*NH*DK*SEQ]; // [B,H,dk,N] (transposed)
__device__ __align__(16) __nv_bfloat16 g_vt_lo[BATCH*NH*DK*SEQ];

__device__ __align__(16) __nv_bfloat16 g_at_hi[M_ROWS*EMBED];    // attention out [B,N,C]
__device__ __align__(16) __nv_bfloat16 g_at_lo[M_ROWS*EMBED];

// ---------------- PTX helpers (plain-target, sm_80-class) -------------------
__device__ __forceinline__ uint32_t smem_u32(const void* p) {
    uint32_t a;
    asm("{ .reg .u64 t; cvta.to.shared.u64 t, %1; cvt.u32.u64 %0, t; }" : "=r"(a) : "l"(p));
    return a;
}
__device__ __forceinline__ void cp16(uint32_t dst, const void* src) {
    asm volatile("cp.async.cg.shared.global [%0], [%1], 16;" :: "r"(dst), "l"(src));
}
#define CP_COMMIT() asm volatile("cp.async.commit_group;" ::: "memory")
#define CP_WAIT0()  asm volatile("cp.async.wait_group 0;" ::: "memory")
#define CP_WAIT1()  asm volatile("cp.async.wait_group 1;" ::: "memory")

__device__ __forceinline__ void ldsm_x4(uint32_t* r, uint32_t addr) {
    asm volatile("ldmatrix.sync.aligned.m8n8.x4.shared.b16 {%0,%1,%2,%3}, [%4];"
                 : "=r"(r[0]), "=r"(r[1]), "=r"(r[2]), "=r"(r[3]) : "r"(addr));
}
__device__ __forceinline__ void ldsm_x2(uint32_t* r, uint32_t addr) {
    asm volatile("ldmatrix.sync.aligned.m8n8.x2.shared.b16 {%0,%1}, [%2];"
                 : "=r"(r[0]), "=r"(r[1]) : "r"(addr));
}
__device__ __forceinline__ void mma_bf16(float* c, const uint32_t* a, const uint32_t* b) {
    asm volatile(
        "mma.sync.aligned.m16n8k16.row.col.f32.bf16.bf16.f32 "
        "{%0,%1,%2,%3}, {%4,%5,%6,%7}, {%8,%9}, {%0,%1,%2,%3};"
        : "+f"(c[0]), "+f"(c[1]), "+f"(c[2]), "+f"(c[3])
        : "r"(a[0]), "r"(a[1]), "r"(a[2]), "r"(a[3]), "r"(b[0]), "r"(b[1]));
}
__device__ __forceinline__ float ex2(float x) {
    float y; asm("ex2.approx.f32 %0, %1;" : "=f"(y) : "f"(x)); return y;
}

// 64B-row XOR swizzle (GEMM tiles, BK=32 -> 64B rows)
__device__ __forceinline__ uint32_t sw_addr(uint32_t base, int row, int col_b16) {
    int chunk = (col_b16 >> 3) ^ ((row >> 1) & 3);
    return base + row * 64 + chunk * 16;
}
// 128B-row XOR swizzle (attention tiles, 64 bf16 = 128B rows). chunk in 16B units.
__device__ __forceinline__ uint32_t swza(uint32_t base, int row, int chunk) {
    return base + row * 128 + ((chunk ^ (row & 7)) * 16);
}

// ---------------- fp32 -> bf16 hi/lo split ----------------------------------
__global__ void split_kernel(const float* __restrict__ src,
                             __nv_bfloat16* __restrict__ hi,
                             __nv_bfloat16* __restrict__ lo, int n4)
{
    int i = blockIdx.x * blockDim.x + threadIdx.x;
    if (i >= n4) return;
    float4 f = ((const float4*)src)[i];
    __nv_bfloat16 h0 = __float2bfloat16(f.x), h1 = __float2bfloat16(f.y);
    __nv_bfloat16 h2 = __float2bfloat16(f.z), h3 = __float2bfloat16(f.w);
    __nv_bfloat16 l0 = __float2bfloat16(f.x - __bfloat162float(h0));
    __nv_bfloat16 l1 = __float2bfloat16(f.y - __bfloat162float(h1));
    __nv_bfloat16 l2 = __float2bfloat16(f.z - __bfloat162float(h2));
    __nv_bfloat16 l3 = __float2bfloat16(f.w - __bfloat162float(h3));
    ((__nv_bfloat162*)hi)[2*i]   = __nv_bfloat162(h0, h1);
    ((__nv_bfloat162*)hi)[2*i+1] = __nv_bfloat162(h2, h3);
    ((__nv_bfloat162*)lo)[2*i]   = __nv_bfloat162(l0, l1);
    ((__nv_bfloat162*)lo)[2*i+1] = __nv_bfloat162(l2, l3);
}

// ---------------- mma.sync split-bf16 GEMM (3-stage pipeline) ---------------
// EPI=0: QKV -> q/k (bf16 hi/lo, [B,H,N,dk], q pre-scaled) + v^T ([B,H,dk,N])
// EPI=1: out-proj -> fp32 Cout
#define BK 32
#define TILE_B (128 * BK * 2)          // 8192 bytes
#define STAGE_B (4 * TILE_B)           // 32768
#define NSTAGE 3
#define SMEM_GEMM (NSTAGE * STAGE_B)   // 98304

template<int EPI>
__global__ void __launch_bounds__(256)
tgemm(const __nv_bfloat16* __restrict__ Ahi, const __nv_bfloat16* __restrict__ Alo,
      const __nv_bfloat16* __restrict__ Bhi, const __nv_bfloat16* __restrict__ Blo,
      const float* __restrict__ bias, float* __restrict__ Cout)
{
    extern __shared__ char smem[];
    const uint32_t sb = smem_u32(smem);

    const int tid = threadIdx.x;
    const int bm = blockIdx.y * 128;
    const int bn = blockIdx.x * 128;

    const int tile = tid >> 6;
    const int slane = tid & 63;
    const __nv_bfloat16* sbase;
    if      (tile == 0) sbase = Ahi + (size_t)bm * EMBED;
    else if (tile == 1) sbase = Alo + (size_t)bm * EMBED;
    else if (tile == 2) sbase = Bhi + (size_t)bn * EMBED;
    else                sbase = Blo + (size_t)bn * EMBED;

    const int wid = tid >> 5;
    const int lane = tid & 31;
    const int wm = (wid >> 2) * 64;
    const int wn = (wid & 3) * 32;

    float acc[4][4][4];
#pragma unroll
    for (int i = 0; i < 4; i++)
#pragma unroll
        for (int j = 0; j < 4; j++)
#pragma unroll
            for (int t = 0; t < 4; t++) acc[i][j][t] = 0.f;

    const int NCHUNK = EMBED / BK;   // 32

    auto issue = [&](int c, int s) {
        const uint32_t tb = sb + s * STAGE_B + tile * TILE_B;
        const int k0 = c * BK;
#pragma unroll
        for (int t = 0; t < 8; t++) {
            const int w = slane + t * 64;
            const int r = w >> 2;
            const int cc = w & 3;
            cp16(sw_addr(tb, r, cc * 8), sbase + (size_t)r * EMBED + k0 + cc * 8);
        }
        CP_COMMIT();
    };

    issue(0, 0);
    issue(1, 1);

    int s = 0;
    for (int c = 0; c < NCHUNK; c++) {
        CP_WAIT1();
        __syncthreads();
        if (c + 2 < NCHUNK) issue(c + 2, (c + 2) % NSTAGE);

        const uint32_t sAhi = sb + s * STAGE_B;
        const uint32_t sAlo = sAhi + TILE_B;
        const uint32_t sBhi = sAhi + 2 * TILE_B;
        const uint32_t sBlo = sAhi + 3 * TILE_B;

#pragma unroll
        for (int ks = 0; ks < 2; ks++) {
            uint32_t ah[4][4], al[4][4], bh[4][2], bl[4][2];
            const int arow = wm + (lane & 15);
            const int acol = ks * 16 + (lane >> 4) * 8;
            const int brow = wn + (lane & 7);
            const int bcol = ks * 16 + ((lane >> 3) & 1) * 8;
#pragma unroll
            for (int mt = 0; mt < 4; mt++) {
                ldsm_x4(ah[mt], sw_addr(sAhi, arow + mt * 16, acol));
                ldsm_x4(al[mt], sw_addr(sAlo, arow + mt * 16, acol));
            }
#pragma unroll
            for (int nt = 0; nt < 4; nt++) {
                ldsm_x2(bh[nt], sw_addr(sBhi, brow + nt * 8, bcol));
                ldsm_x2(bl[nt], sw_addr(sBlo, brow + nt * 8, bcol));
            }
#pragma unroll
            for (int mt = 0; mt < 4; mt++)
#pragma unroll
                for (int nt = 0; nt < 4; nt++) {
                    mma_bf16(acc[mt][nt], ah[mt], bh[nt]);
                    mma_bf16(acc[mt][nt], ah[mt], bl[nt]);
                    mma_bf16(acc[mt][nt], al[mt], bh[nt]);
                }
        }
        s = (s + 1 == NSTAGE) ? 0 : s + 1;
    }

#pragma unroll
    for (int mt = 0; mt < 4; mt++) {
#pragma unroll
        for (int half = 0; half < 2; half++) {
            const int m = bm + wm + mt * 16 + (lane >> 2) + half * 8;
            const int bi = m >> 11;
            const int tt = m & 2047;
#pragma unroll
            for (int nt = 0; nt < 4; nt++) {
                const int n0 = bn + wn + nt * 8 + (lane & 3) * 2;
                float v0 = acc[mt][nt][half * 2 + 0] + bias[n0];
                float v1 = acc[mt][nt][half * 2 + 1] + bias[n0 + 1];
                if (EPI == 0) {
                    const int which = n0 >> 10;
                    const int cc = n0 & 1023;
                    const int h = cc >> 6;
                    const int d = cc & 63;
                    const int bh = bi * NH + h;
                    if (which == 0) { v0 *= QSCALE; v1 *= QSCALE; }
                    __nv_bfloat16 h0 = __float2bfloat16(v0);
                    __nv_bfloat16 h1 = __float2bfloat16(v1);
                    __nv_bfloat16 l0 = __float2bfloat16(v0 - __bfloat162float(h0));
                    __nv_bfloat16 l1 = __float2bfloat16(v1 - __bfloat162float(h1));
                    if (which < 2) {
                        __nv_bfloat16* dhi = which ? g_k_hi : g_q_hi;
                        __nv_bfloat16* dlo = which ? g_k_lo : g_q_lo;
                        const size_t idx = ((size_t)bh * SEQ + tt) * DK + d;
                        *(__nv_bfloat162*)(dhi + idx) = __nv_bfloat162(h0, h1);
                        *(__nv_bfloat162*)(dlo + idx) = __nv_bfloat162(l0, l1);
                    } else {
                        const size_t idx = ((size_t)bh * DK + d) * SEQ + tt;
                        g_vt_hi[idx] = h0; g_vt_hi[idx + SEQ] = h1;
                        g_vt_lo[idx] = l0; g_vt_lo[idx + SEQ] = l1;
                    }
                } else {
                    Cout[(size_t)m * EMBED + n0]     = v0;
                    Cout[(size_t)m * EMBED + n0 + 1] = v1;
                }
            }
        }
    }
}

// ---------------- tensor-core causal flash attention ------------------------
// CTA: 128 queries, 8 warps x 16 rows (R5 per-warp register footprint).
// Key tiles of 64, 2-stage cp.async.
// smem: Q hi/lo (32K) + 2 stages x {Khi,Klo,VThi,VTlo} (32K) = 96K
#define ATT_SMEM (32768 + 2 * 32768)

__global__ void __launch_bounds__(256) attn_mma()
{
    extern __shared__ char smem[];
    const uint32_t sb = smem_u32(smem);
    const uint32_t qhi_s = sb, qlo_s = sb + 16384;
    const uint32_t stage0 = sb + 32768;

    const int tid = threadIdx.x;
    const int lane = tid & 31;
    const int wid = tid >> 5;          // 0..7
    const int g = lane >> 2;
    const int tg = lane & 3;
    const int bh = blockIdx.y;
    const int qb = (int)(gridDim.x - 1 - blockIdx.x);  // heavy blocks first

    const __nv_bfloat16* qhi_g = g_q_hi + ((size_t)bh * SEQ + qb * 128) * DK;
    const __nv_bfloat16* qlo_g = g_q_lo + ((size_t)bh * SEQ + qb * 128) * DK;
    const __nv_bfloat16* khi_g = g_k_hi + (size_t)bh * SEQ * DK;
    const __nv_bfloat16* klo_g = g_k_lo + (size_t)bh * SEQ * DK;
    const __nv_bfloat16* vthi_g = g_vt_hi + (size_t)bh * DK * SEQ;
    const __nv_bfloat16* vtlo_g = g_vt_lo + (size_t)bh * DK * SEQ;

    // stage Q (hi+lo): 128 rows x 128B each buffer = 1024 chunks; 256 threads
#pragma unroll
    for (int i = 0; i < 4; i++) {
        const int w = tid + i * 256;       // 0..1023
        const int r = w >> 3, c = w & 7;
        cp16(swza(qhi_s, r, c), qhi_g + (size_t)r * DK + c * 8);
        cp16(swza(qlo_s, r, c), qlo_g + (size_t)r * DK + c * 8);
    }
    CP_COMMIT();

    auto issue_tile = [&](int kt, int s) {
        const uint32_t st = stage0 + s * 32768;
        const int k0 = kt * 64;
#pragma unroll
        for (int i = 0; i < 2; i++) {
            const int w = tid + i * 256;   // 0..511
            const int r = w >> 3, c = w & 7;
            const uint32_t off = r * 128 + ((c ^ (r & 7)) * 16);
            cp16(st + off,         khi_g + (size_t)(k0 + r) * DK + c * 8);
            cp16(st + 8192 + off,  klo_g + (size_t)(k0 + r) * DK + c * 8);
            cp16(st + 16384 + off, vthi_g + (size_t)r * SEQ + k0 + c * 8);
            cp16(st + 24576 + off, vtlo_g + (size_t)r * SEQ + k0 + c * 8);
        }
        CP_COMMIT();
    };

    issue_tile(0, 0);

    uint32_t qh[4][4], ql[4][4];
    float oacc[8][4];
#pragma unroll
    for (int nt = 0; nt < 8; nt++)
#pragma unroll
        for (int t = 0; t < 4; t++) oacc[nt][t] = 0.f;
    float m0 = -1e30f, m1 = -1e30f, l0 = 0.f, l1 = 0.f;

    const int ntiles = 2 * qb + 2;     // 64-key tiles covering 128*(qb+1) keys
    const int wrow = wid * 16;          // warp's first query row within CTA

    for (int kt = 0; kt < ntiles; kt++) {
        const int s = kt & 1;
        if (kt + 1 < ntiles) { issue_tile(kt + 1, s ^ 1); CP_WAIT1(); }
        else                 { CP_WAIT0(); }
        __syncthreads();

        if (kt == 0) {
            const int arow = wrow + (lane & 15);
            const int ach = lane >> 4;
#pragma unroll
            for (int kc = 0; kc < 4; kc++) {
                ldsm_x4(qh[kc], swza(qhi_s, arow, kc * 2 + ach));
                ldsm_x4(ql[kc], swza(qlo_s, arow, kc * 2 + ach));
            }
        }

        // per-warp early-exit: whole tile above this warp's last query row
        const bool active = (kt * 64) <= (qb * 128 + wrow + 15);

        if (active) {
            const uint32_t sK   = stage0 + s * 32768;
            const uint32_t sKl  = sK + 8192;
            const uint32_t sVT  = sK + 16384;
            const uint32_t sVTl = sK + 24576;
            const int br = lane & 7;
            const int bc = (lane >> 3) & 1;

            // ---- S = Q K^T ----
            float sacc[8][4];
#pragma unroll
            for (int nt = 0; nt < 8; nt++)
#pragma unroll
                for (int t = 0; t < 4; t++) sacc[nt][t] = 0.f;

#pragma unroll
            for (int kc = 0; kc < 4; kc++) {
                uint32_t bhf[8][2], blf[8][2];
#pragma unroll
                for (int nt = 0; nt < 8; nt++) {
                    ldsm_x2(bhf[nt], swza(sK,  nt * 8 + br, kc * 2 + bc));
                    ldsm_x2(blf[nt], swza(sKl, nt * 8 + br, kc * 2 + bc));
                }
#pragma unroll
                for (int nt = 0; nt < 8; nt++) {
                    mma_bf16(sacc[nt], qh[kc], bhf[nt]);
                    mma_bf16(sacc[nt], qh[kc], blf[nt]);
                    mma_bf16(sacc[nt], ql[kc], bhf[nt]);
                }
            }

            // ---- causal mask (only tiles overlapping the diagonal) ----
            if (kt * 64 + 63 > qb * 128 + wrow) {
#pragma unroll
                for (int nt = 0; nt < 8; nt++)
#pragma unroll
                    for (int idx = 0; idx < 4; idx++) {
                        const int key = kt * 64 + nt * 8 + tg * 2 + (idx & 1);
                        const int qr  = qb * 128 + wrow + g + (idx >> 1) * 8;
                        if (key > qr) sacc[nt][idx] = -1e30f;
                    }
            }

            // ---- online softmax (log2 domain) ----
            float mx0 = -1e30f, mx1 = -1e30f;
#pragma unroll
            for (int nt = 0; nt < 8; nt++) {
                mx0 = fmaxf(mx0, fmaxf(sacc[nt][0], sacc[nt][1]));
                mx1 = fmaxf(mx1, fmaxf(sacc[nt][2], sacc[nt][3]));
            }
            mx0 = fmaxf(mx0, __shfl_xor_sync(0xffffffffu, mx0, 1));
            mx0 = fmaxf(mx0, __shfl_xor_sync(0xffffffffu, mx0, 2));
            mx1 = fmaxf(mx1, __shfl_xor_sync(0xffffffffu, mx1, 1));
            mx1 = fmaxf(mx1, __shfl_xor_sync(0xffffffffu, mx1, 2));

            const float mn0 = fmaxf(m0, mx0);
            const float mn1 = fmaxf(m1, mx1);
            const float a0 = ex2(m0 - mn0);
            const float a1 = ex2(m1 - mn1);
            m0 = mn0; m1 = mn1;
            l0 *= a0; l1 *= a1;
#pragma unroll
            for (int nt = 0; nt < 8; nt++) {
                oacc[nt][0] *= a0; oacc[nt][1] *= a0;
                oacc[nt][2] *= a1; oacc[nt][3] *= a1;
            }

            uint32_t ph[4][4], pl[4][4];
            float ps0 = 0.f, ps1 = 0.f;
#pragma unroll
            for (int nt = 0; nt < 8; nt++) {
                const float p0 = ex2(sacc[nt][0] - mn0);
                const float p1 = ex2(sacc[nt][1] - mn0);
                const float p2 = ex2(sacc[nt][2] - mn1);
                const float p3 = ex2(sacc[nt][3] - mn1);
                ps0 += p0 + p1; ps1 += p2 + p3;
                const int kc = nt >> 1;
                const int r = (nt & 1) * 2;
                __nv_bfloat162 hp01 = __floats2bfloat162_rn(p0, p1);
                __nv_bfloat162 hp23 = __floats2bfloat162_rn(p2, p3);
                __nv_bfloat162 lp01 = __floats2bfloat162_rn(
                    p0 - __bfloat162float(hp01.x), p1 - __bfloat162float(hp01.y));
                __nv_bfloat162 lp23 = __floats2bfloat162_rn(
                    p2 - __bfloat162float(hp23.x), p3 - __bfloat162float(hp23.y));
                ph[kc][r + 0] = *(uint32_t*)&hp01;
                ph[kc][r + 1] = *(uint32_t*)&hp23;
                pl[kc][r + 0] = *(uint32_t*)&lp01;
                pl[kc][r + 1] = *(uint32_t*)&lp23;
            }
            // quad-reduce row sums (l is a row statistic)
            ps0 += __shfl_xor_sync(0xffffffffu, ps0, 1);
            ps0 += __shfl_xor_sync(0xffffffffu, ps0, 2);
            ps1 += __shfl_xor_sync(0xffffffffu, ps1, 1);
            ps1 += __shfl_xor_sync(0xffffffffu, ps1, 2);
            l0 += ps0; l1 += ps1;

            // ---- O += P V ----
#pragma unroll
            for (int kc = 0; kc < 4; kc++) {
                uint32_t vh[8][2], vl[8][2];
#pragma unroll
                for (int nt = 0; nt < 8; nt++) {
                    ldsm_x2(vh[nt], swza(sVT,  nt * 8 + br, kc * 2 + bc));
                    ldsm_x2(vl[nt], swza(sVTl, nt * 8 + br, kc * 2 + bc));
                }
#pragma unroll
                for (int nt = 0; nt < 8; nt++) {
                    mma_bf16(oacc[nt], ph[kc], vh[nt]);
                    mma_bf16(oacc[nt], ph[kc], vl[nt]);
                    mma_bf16(oacc[nt], pl[kc], vh[nt]);
                }
            }
        }
        __syncthreads();   // protect stage before re-staging
    }

    // ---- normalize + write bf16 hi/lo [B,N,C] ----
    const float inv0 = 1.0f / l0;
    const float inv1 = 1.0f / l1;
    const int bi = bh >> 4;
    const int h  = bh & 15;
    const int row0 = bi * SEQ + qb * 128 + wrow + g;
#pragma unroll
    for (int nt = 0; nt < 8; nt++) {
        const int col = h * 64 + nt * 8 + tg * 2;
        {
            const float v0 = oacc[nt][0] * inv0, v1 = oacc[nt][1] * inv0;
            __nv_bfloat162 hp = __floats2bfloat162_rn(v0, v1);
            __nv_bfloat162 lp = __floats2bfloat162_rn(
                v0 - __bfloat162float(hp.x), v1 - __bfloat162float(hp.y));
            *(__nv_bfloat162*)(g_at_hi + (size_t)row0 * EMBED + col) = hp;
            *(__nv_bfloat162*)(g_at_lo + (size_t)row0 * EMBED + col) = lp;
        }
        {
            const float v0 = oacc[nt][2] * inv1, v1 = oacc[nt][3] * inv1;
            __nv_bfloat162 hp = __floats2bfloat162_rn(v0, v1);
            __nv_bfloat162 lp = __floats2bfloat162_rn(
                v0 - __bfloat162float(hp.x), v1 - __bfloat162float(hp.y));
            *(__nv_bfloat162*)(g_at_hi + (size_t)(row0 + 8) * EMBED + col) = hp;
            *(__nv_bfloat162*)(g_at_lo + (size_t)(row0 + 8) * EMBED + col) = lp;
        }
    }
}

// ---------------------------------------------------------------------------
extern "C" void kernel_launch(void* const* d_in, const int* in_sizes, int n_in,
                              void* d_out, int out_size)
{
    const float* x     = (const float*)d_in[0];
    const float* w_qkv = (const float*)d_in[1];
    const float* b_qkv = (const float*)d_in[2];
    const float* w_o   = (const float*)d_in[3];
    const float* b_o   = (const float*)d_in[4];
    float* out = (float*)d_out;

    void *xh, *xl, *qh, *ql, *oh, *ol, *ah, *al;
    cudaGetSymbolAddress(&xh, g_x_hi);    cudaGetSymbolAddress(&xl, g_x_lo);
    cudaGetSymbolAddress(&qh, g_wqkv_hi); cudaGetSymbolAddress(&ql, g_wqkv_lo);
    cudaGetSymbolAddress(&oh, g_wo_hi);   cudaGetSymbolAddress(&ol, g_wo_lo);
    cudaGetSymbolAddress(&ah, g_at_hi);   cudaGetSymbolAddress(&al, g_at_lo);

    cudaFuncSetAttribute(tgemm<0>, cudaFuncAttributeMaxDynamicSharedMemorySize, SMEM_GEMM);
    cudaFuncSetAttribute(tgemm<1>, cudaFuncAttributeMaxDynamicSharedMemorySize, SMEM_GEMM);
    cudaFuncSetAttribute(attn_mma, cudaFuncAttributeMaxDynamicSharedMemorySize, ATT_SMEM);

    // split inputs to bf16 hi/lo
    {
        int n4 = M_ROWS * EMBED / 4;
        split_kernel<<<(n4 + 255) / 256, 256>>>(x, (__nv_bfloat16*)xh, (__nv_bfloat16*)xl, n4);
        n4 = QKV_COLS * EMBED / 4;
        split_kernel<<<(n4 + 255) / 256, 256>>>(w_qkv, (__nv_bfloat16*)qh, (__nv_bfloat16*)ql, n4);
        n4 = EMBED * EMBED / 4;
        split_kernel<<<(n4 + 255) / 256, 256>>>(w_o, (__nv_bfloat16*)oh, (__nv_bfloat16*)ol, n4);
    }

    // QKV projection -> q/k hi/lo + v^T hi/lo
    tgemm<0><<<dim3(QKV_COLS / 128, M_ROWS / 128), 256, SMEM_GEMM>>>(
        (const __nv_bfloat16*)xh, (const __nv_bfloat16*)xl,
        (const __nv_bfloat16*)qh, (const __nv_bfloat16*)ql, b_qkv, nullptr);

    // tensor-core flash attention -> g_at hi/lo
    attn_mma<<<dim3(SEQ / 128, BATCH * NH), 256, ATT_SMEM>>>();

    // output projection -> d_out
    tgemm<1><<<dim3(EMBED / 128, M_ROWS / 128), 256, SMEM_GEMM>>>(
        (const __nv_bfloat16*)ah, (const __nv_bfloat16*)al,
        (const __nv_bfloat16*)oh, (const __nv_bfloat16*)ol, b_o, out);
}

// round 8
// speedup vs baseline: 1.3458x; 1.3458x over previous
#include <cuda_runtime.h>
#include <cuda_bf16.h>
#include <cuda_fp16.h>
#include <math.h>
#include <stdint.h>

#define EMBED 1024
#define NH 16
#define DK 64
#define BATCH 2
#define SEQ 2048
#define M_ROWS (BATCH*SEQ)      // 4096
#define QKV_COLS (3*EMBED)      // 3072

// log2(e) / sqrt(1024) — folded into Q at the QKV epilogue
#define QSCALE 0.0450842200f

// ---------------- scratch (__device__ globals) ------------------------------
__device__ __align__(16) __nv_bfloat16 g_x_hi[M_ROWS*EMBED];
__device__ __align__(16) __nv_bfloat16 g_x_lo[M_ROWS*EMBED];
__device__ __align__(16) __nv_bfloat16 g_wqkv_hi[QKV_COLS*EMBED];
__device__ __align__(16) __nv_bfloat16 g_wqkv_lo[QKV_COLS*EMBED];
__device__ __align__(16) __nv_bfloat16 g_wo_hi[EMBED*EMBED];
__device__ __align__(16) __nv_bfloat16 g_wo_lo[EMBED*EMBED];

__device__ __align__(16) __half g_qf[BATCH*NH*SEQ*DK];   // [B,H,N,dk] (pre-scaled)
__device__ __align__(16) __half g_kf[BATCH*NH*SEQ*DK];   // [B,H,N,dk]
__device__ __align__(16) __half g_vtf[BATCH*NH*DK*SEQ];  // [B,H,dk,N] (transposed)

__device__ __align__(16) __nv_bfloat16 g_at_hi[M_ROWS*EMBED];    // attention out [B,N,C]
__device__ __align__(16) __nv_bfloat16 g_at_lo[M_ROWS*EMBED];

// ---------------- PTX helpers (plain-target, sm_80-class) -------------------
__device__ __forceinline__ uint32_t smem_u32(const void* p) {
    uint32_t a;
    asm("{ .reg .u64 t; cvta.to.shared.u64 t, %1; cvt.u32.u64 %0, t; }" : "=r"(a) : "l"(p));
    return a;
}
__device__ __forceinline__ void cp16(uint32_t dst, const void* src) {
    asm volatile("cp.async.cg.shared.global [%0], [%1], 16;" :: "r"(dst), "l"(src));
}
#define CP_COMMIT() asm volatile("cp.async.commit_group;" ::: "memory")
#define CP_WAIT0()  asm volatile("cp.async.wait_group 0;" ::: "memory")
#define CP_WAIT1()  asm volatile("cp.async.wait_group 1;" ::: "memory")

__device__ __forceinline__ void ldsm_x4(uint32_t* r, uint32_t addr) {
    asm volatile("ldmatrix.sync.aligned.m8n8.x4.shared.b16 {%0,%1,%2,%3}, [%4];"
                 : "=r"(r[0]), "=r"(r[1]), "=r"(r[2]), "=r"(r[3]) : "r"(addr));
}
__device__ __forceinline__ void ldsm_x2(uint32_t* r, uint32_t addr) {
    asm volatile("ldmatrix.sync.aligned.m8n8.x2.shared.b16 {%0,%1}, [%2];"
                 : "=r"(r[0]), "=r"(r[1]) : "r"(addr));
}
__device__ __forceinline__ void mma_bf16(float* c, const uint32_t* a, const uint32_t* b) {
    asm volatile(
        "mma.sync.aligned.m16n8k16.row.col.f32.bf16.bf16.f32 "
        "{%0,%1,%2,%3}, {%4,%5,%6,%7}, {%8,%9}, {%0,%1,%2,%3};"
        : "+f"(c[0]), "+f"(c[1]), "+f"(c[2]), "+f"(c[3])
        : "r"(a[0]), "r"(a[1]), "r"(a[2]), "r"(a[3]), "r"(b[0]), "r"(b[1]));
}
__device__ __forceinline__ void mma_f16(float* c, const uint32_t* a, const uint32_t* b) {
    asm volatile(
        "mma.sync.aligned.m16n8k16.row.col.f32.f16.f16.f32 "
        "{%0,%1,%2,%3}, {%4,%5,%6,%7}, {%8,%9}, {%0,%1,%2,%3};"
        : "+f"(c[0]), "+f"(c[1]), "+f"(c[2]), "+f"(c[3])
        : "r"(a[0]), "r"(a[1]), "r"(a[2]), "r"(a[3]), "r"(b[0]), "r"(b[1]));
}
__device__ __forceinline__ float ex2(float x) {
    float y; asm("ex2.approx.f32 %0, %1;" : "=f"(y) : "f"(x)); return y;
}

// 64B-row XOR swizzle (GEMM tiles, BK=32 -> 64B rows)
__device__ __forceinline__ uint32_t sw_addr(uint32_t base, int row, int col_b16) {
    int chunk = (col_b16 >> 3) ^ ((row >> 1) & 3);
    return base + row * 64 + chunk * 16;
}
// 128B-row XOR swizzle (attention tiles, 64 fp16 = 128B rows). chunk in 16B units.
__device__ __forceinline__ uint32_t swza(uint32_t base, int row, int chunk) {
    return base + row * 128 + ((chunk ^ (row & 7)) * 16);
}

// ---------------- fp32 -> bf16 hi/lo split ----------------------------------
__global__ void split_kernel(const float* __restrict__ src,
                             __nv_bfloat16* __restrict__ hi,
                             __nv_bfloat16* __restrict__ lo, int n4)
{
    int i = blockIdx.x * blockDim.x + threadIdx.x;
    if (i >= n4) return;
    float4 f = ((const float4*)src)[i];
    __nv_bfloat16 h0 = __float2bfloat16(f.x), h1 = __float2bfloat16(f.y);
    __nv_bfloat16 h2 = __float2bfloat16(f.z), h3 = __float2bfloat16(f.w);
    __nv_bfloat16 l0 = __float2bfloat16(f.x - __bfloat162float(h0));
    __nv_bfloat16 l1 = __float2bfloat16(f.y - __bfloat162float(h1));
    __nv_bfloat16 l2 = __float2bfloat16(f.z - __bfloat162float(h2));
    __nv_bfloat16 l3 = __float2bfloat16(f.w - __bfloat162float(h3));
    ((__nv_bfloat162*)hi)[2*i]   = __nv_bfloat162(h0, h1);
    ((__nv_bfloat162*)hi)[2*i+1] = __nv_bfloat162(h2, h3);
    ((__nv_bfloat162*)lo)[2*i]   = __nv_bfloat162(l0, l1);
    ((__nv_bfloat162*)lo)[2*i+1] = __nv_bfloat162(l2, l3);
}

// ---------------- mma.sync split-bf16 GEMM (3-stage pipeline) ---------------
// EPI=0: QKV -> q/k fp16 ([B,H,N,dk], q pre-scaled) + v^T fp16 ([B,H,dk,N])
// EPI=1: out-proj -> fp32 Cout
#define BK 32
#define TILE_B (128 * BK * 2)          // 8192 bytes
#define STAGE_B (4 * TILE_B)           // 32768
#define NSTAGE 3
#define SMEM_GEMM (NSTAGE * STAGE_B)   // 98304

template<int EPI>
__global__ void __launch_bounds__(256)
tgemm(const __nv_bfloat16* __restrict__ Ahi, const __nv_bfloat16* __restrict__ Alo,
      const __nv_bfloat16* __restrict__ Bhi, const __nv_bfloat16* __restrict__ Blo,
      const float* __restrict__ bias, float* __restrict__ Cout)
{
    extern __shared__ char smem[];
    const uint32_t sb = smem_u32(smem);

    const int tid = threadIdx.x;
    const int bm = blockIdx.y * 128;
    const int bn = blockIdx.x * 128;

    const int tile = tid >> 6;
    const int slane = tid & 63;
    const __nv_bfloat16* sbase;
    if      (tile == 0) sbase = Ahi + (size_t)bm * EMBED;
    else if (tile == 1) sbase = Alo + (size_t)bm * EMBED;
    else if (tile == 2) sbase = Bhi + (size_t)bn * EMBED;
    else                sbase = Blo + (size_t)bn * EMBED;

    const int wid = tid >> 5;
    const int lane = tid & 31;
    const int wm = (wid >> 2) * 64;
    const int wn = (wid & 3) * 32;

    float acc[4][4][4];
#pragma unroll
    for (int i = 0; i < 4; i++)
#pragma unroll
        for (int j = 0; j < 4; j++)
#pragma unroll
            for (int t = 0; t < 4; t++) acc[i][j][t] = 0.f;

    const int NCHUNK = EMBED / BK;   // 32

    auto issue = [&](int c, int s) {
        const uint32_t tb = sb + s * STAGE_B + tile * TILE_B;
        const int k0 = c * BK;
#pragma unroll
        for (int t = 0; t < 8; t++) {
            const int w = slane + t * 64;
            const int r = w >> 2;
            const int cc = w & 3;
            cp16(sw_addr(tb, r, cc * 8), sbase + (size_t)r * EMBED + k0 + cc * 8);
        }
        CP_COMMIT();
    };

    issue(0, 0);
    issue(1, 1);

    int s = 0;
    for (int c = 0; c < NCHUNK; c++) {
        CP_WAIT1();
        __syncthreads();
        if (c + 2 < NCHUNK) issue(c + 2, (c + 2) % NSTAGE);

        const uint32_t sAhi = sb + s * STAGE_B;
        const uint32_t sAlo = sAhi + TILE_B;
        const uint32_t sBhi = sAhi + 2 * TILE_B;
        const uint32_t sBlo = sAhi + 3 * TILE_B;

#pragma unroll
        for (int ks = 0; ks < 2; ks++) {
            uint32_t ah[4][4], al[4][4], bh[4][2], bl[4][2];
            const int arow = wm + (lane & 15);
            const int acol = ks * 16 + (lane >> 4) * 8;
            const int brow = wn + (lane & 7);
            const int bcol = ks * 16 + ((lane >> 3) & 1) * 8;
#pragma unroll
            for (int mt = 0; mt < 4; mt++) {
                ldsm_x4(ah[mt], sw_addr(sAhi, arow + mt * 16, acol));
                ldsm_x4(al[mt], sw_addr(sAlo, arow + mt * 16, acol));
            }
#pragma unroll
            for (int nt = 0; nt < 4; nt++) {
                ldsm_x2(bh[nt], sw_addr(sBhi, brow + nt * 8, bcol));
                ldsm_x2(bl[nt], sw_addr(sBlo, brow + nt * 8, bcol));
            }
#pragma unroll
            for (int mt = 0; mt < 4; mt++)
#pragma unroll
                for (int nt = 0; nt < 4; nt++) {
                    mma_bf16(acc[mt][nt], ah[mt], bh[nt]);
                    mma_bf16(acc[mt][nt], ah[mt], bl[nt]);
                    mma_bf16(acc[mt][nt], al[mt], bh[nt]);
                }
        }
        s = (s + 1 == NSTAGE) ? 0 : s + 1;
    }

#pragma unroll
    for (int mt = 0; mt < 4; mt++) {
#pragma unroll
        for (int half = 0; half < 2; half++) {
            const int m = bm + wm + mt * 16 + (lane >> 2) + half * 8;
            const int bi = m >> 11;
            const int tt = m & 2047;
#pragma unroll
            for (int nt = 0; nt < 4; nt++) {
                const int n0 = bn + wn + nt * 8 + (lane & 3) * 2;
                float v0 = acc[mt][nt][half * 2 + 0] + bias[n0];
                float v1 = acc[mt][nt][half * 2 + 1] + bias[n0 + 1];
                if (EPI == 0) {
                    const int which = n0 >> 10;
                    const int cc = n0 & 1023;
                    const int h = cc >> 6;
                    const int d = cc & 63;
                    const int bh = bi * NH + h;
                    if (which == 0) { v0 *= QSCALE; v1 *= QSCALE; }
                    if (which < 2) {
                        __half* dst = which ? g_kf : g_qf;
                        const size_t idx = ((size_t)bh * SEQ + tt) * DK + d;
                        *(__half2*)(dst + idx) = __floats2half2_rn(v0, v1);
                    } else {
                        const size_t idx = ((size_t)bh * DK + d) * SEQ + tt;
                        g_vtf[idx]       = __float2half_rn(v0);
                        g_vtf[idx + SEQ] = __float2half_rn(v1);
                    }
                } else {
                    Cout[(size_t)m * EMBED + n0]     = v0;
                    Cout[(size_t)m * EMBED + n0 + 1] = v1;
                }
            }
        }
    }
}

// ---------------- tensor-core causal flash attention (fp16, single-pass) ----
// CTA: 64 queries (4 warps x 16 rows), key tiles of 64, 2-stage cp.async.
// smem: Q (8K) + 2 stages x {K(8K), VT(8K)} = 40K -> high occupancy
#define ATT_SMEM (8192 + 2 * 16384)

__global__ void __launch_bounds__(128) attn_mma()
{
    extern __shared__ char smem[];
    const uint32_t sb = smem_u32(smem);
    const uint32_t q_s = sb;
    const uint32_t stage0 = sb + 8192;

    const int tid = threadIdx.x;
    const int lane = tid & 31;
    const int wid = tid >> 5;
    const int g = lane >> 2;
    const int tg = lane & 3;
    const int bh = blockIdx.y;
    const int qb = (int)(gridDim.x - 1 - blockIdx.x);   // heavy blocks first

    const __half* q_g  = g_qf  + ((size_t)bh * SEQ + qb * 64) * DK;
    const __half* k_g  = g_kf  + (size_t)bh * SEQ * DK;
    const __half* vt_g = g_vtf + (size_t)bh * DK * SEQ;

    // stage Q: 64 rows x 128B = 512 chunks, 128 threads x 4
#pragma unroll
    for (int i = 0; i < 4; i++) {
        const int w = tid + i * 128;
        const int r = w >> 3, c = w & 7;
        cp16(swza(q_s, r, c), q_g + (size_t)r * DK + c * 8);
    }
    CP_COMMIT();

    auto issue_tile = [&](int kt, int s) {
        const uint32_t st = stage0 + s * 16384;
        const int k0 = kt * 64;
#pragma unroll
        for (int i = 0; i < 4; i++) {
            const int w = tid + i * 128;
            const int r = w >> 3, c = w & 7;
            const uint32_t off = r * 128 + ((c ^ (r & 7)) * 16);
            cp16(st + off,        k_g + (size_t)(k0 + r) * DK + c * 8);
            cp16(st + 8192 + off, vt_g + (size_t)r * SEQ + k0 + c * 8);
        }
        CP_COMMIT();
    };

    issue_tile(0, 0);

    uint32_t qf[4][4];
    float oacc[8][4];
#pragma unroll
    for (int nt = 0; nt < 8; nt++)
#pragma unroll
        for (int t = 0; t < 4; t++) oacc[nt][t] = 0.f;
    float m0 = -1e30f, m1 = -1e30f, l0 = 0.f, l1 = 0.f;

    for (int kt = 0; kt <= qb; kt++) {
        const int s = kt & 1;
        if (kt < qb) { issue_tile(kt + 1, s ^ 1); CP_WAIT1(); }
        else         { CP_WAIT0(); }
        __syncthreads();

        if (kt == 0) {
            const int arow = wid * 16 + (lane & 15);
            const int ach = lane >> 4;
#pragma unroll
            for (int kc = 0; kc < 4; kc++)
                ldsm_x4(qf[kc], swza(q_s, arow, kc * 2 + ach));
        }

        const uint32_t sK  = stage0 + s * 16384;
        const uint32_t sVT = sK + 8192;
        const int br = lane & 7;
        const int bc = (lane >> 3) & 1;

        // ---- S = Q K^T (single fp16 pass; scale & log2e folded into Q) ----
        float sacc[8][4];
#pragma unroll
        for (int nt = 0; nt < 8; nt++)
#pragma unroll
            for (int t = 0; t < 4; t++) sacc[nt][t] = 0.f;

#pragma unroll
        for (int kc = 0; kc < 4; kc++) {
            uint32_t bf[8][2];
#pragma unroll
            for (int nt = 0; nt < 8; nt++)
                ldsm_x2(bf[nt], swza(sK, nt * 8 + br, kc * 2 + bc));
#pragma unroll
            for (int nt = 0; nt < 8; nt++)
                mma_f16(sacc[nt], qf[kc], bf[nt]);
        }

        // ---- causal mask (diagonal tile only) ----
        if (kt == qb) {
#pragma unroll
            for (int nt = 0; nt < 8; nt++)
#pragma unroll
                for (int idx = 0; idx < 4; idx++) {
                    const int key = nt * 8 + tg * 2 + (idx & 1);
                    const int qr  = wid * 16 + g + (idx >> 1) * 8;
                    if (key > qr) sacc[nt][idx] = -1e30f;
                }
        }

        // ---- online softmax (log2 domain) ----
        float mx0 = -1e30f, mx1 = -1e30f;
#pragma unroll
        for (int nt = 0; nt < 8; nt++) {
            mx0 = fmaxf(mx0, fmaxf(sacc[nt][0], sacc[nt][1]));
            mx1 = fmaxf(mx1, fmaxf(sacc[nt][2], sacc[nt][3]));
        }
        mx0 = fmaxf(mx0, __shfl_xor_sync(0xffffffffu, mx0, 1));
        mx0 = fmaxf(mx0, __shfl_xor_sync(0xffffffffu, mx0, 2));
        mx1 = fmaxf(mx1, __shfl_xor_sync(0xffffffffu, mx1, 1));
        mx1 = fmaxf(mx1, __shfl_xor_sync(0xffffffffu, mx1, 2));

        const float mn0 = fmaxf(m0, mx0);
        const float mn1 = fmaxf(m1, mx1);
        const float a0 = ex2(m0 - mn0);
        const float a1 = ex2(m1 - mn1);
        m0 = mn0; m1 = mn1;
        l0 *= a0; l1 *= a1;
#pragma unroll
        for (int nt = 0; nt < 8; nt++) {
            oacc[nt][0] *= a0; oacc[nt][1] *= a0;
            oacc[nt][2] *= a1; oacc[nt][3] *= a1;
        }

        uint32_t pf[4][4];
        float ps0 = 0.f, ps1 = 0.f;
#pragma unroll
        for (int nt = 0; nt < 8; nt++) {
            const float p0 = ex2(sacc[nt][0] - mn0);
            const float p1 = ex2(sacc[nt][1] - mn0);
            const float p2 = ex2(sacc[nt][2] - mn1);
            const float p3 = ex2(sacc[nt][3] - mn1);
            ps0 += p0 + p1; ps1 += p2 + p3;
            const int kc = nt >> 1;
            const int r = (nt & 1) * 2;
            __half2 hp01 = __floats2half2_rn(p0, p1);
            __half2 hp23 = __floats2half2_rn(p2, p3);
            pf[kc][r + 0] = *(uint32_t*)&hp01;   // A-frag a0/a1: row g, cols k/k+1
            pf[kc][r + 1] = *(uint32_t*)&hp23;   // A-frag a2/a3: row g+8
        }
        // quad-reduce row sums (l is a row statistic)
        ps0 += __shfl_xor_sync(0xffffffffu, ps0, 1);
        ps0 += __shfl_xor_sync(0xffffffffu, ps0, 2);
        ps1 += __shfl_xor_sync(0xffffffffu, ps1, 1);
        ps1 += __shfl_xor_sync(0xffffffffu, ps1, 2);
        l0 += ps0; l1 += ps1;

        // ---- O += P V (single fp16 pass) ----
#pragma unroll
        for (int kc = 0; kc < 4; kc++) {
            uint32_t vf[8][2];
#pragma unroll
            for (int nt = 0; nt < 8; nt++)
                ldsm_x2(vf[nt], swza(sVT, nt * 8 + br, kc * 2 + bc));
#pragma unroll
            for (int nt = 0; nt < 8; nt++)
                mma_f16(oacc[nt], pf[kc], vf[nt]);
        }
        __syncthreads();   // protect stage before re-staging
    }

    // ---- normalize + write bf16 hi/lo [B,N,C] ----
    const float inv0 = 1.0f / l0;
    const float inv1 = 1.0f / l1;
    const int bi = bh >> 4;
    const int h  = bh & 15;
    const int row0 = bi * SEQ + qb * 64 + wid * 16 + g;
#pragma unroll
    for (int nt = 0; nt < 8; nt++) {
        const int col = h * 64 + nt * 8 + tg * 2;
        {
            const float v0 = oacc[nt][0] * inv0, v1 = oacc[nt][1] * inv0;
            __nv_bfloat162 hp = __floats2bfloat162_rn(v0, v1);
            __nv_bfloat162 lp = __floats2bfloat162_rn(
                v0 - __bfloat162float(hp.x), v1 - __bfloat162float(hp.y));
            *(__nv_bfloat162*)(g_at_hi + (size_t)row0 * EMBED + col) = hp;
            *(__nv_bfloat162*)(g_at_lo + (size_t)row0 * EMBED + col) = lp;
        }
        {
            const float v0 = oacc[nt][2] * inv1, v1 = oacc[nt][3] * inv1;
            __nv_bfloat162 hp = __floats2bfloat162_rn(v0, v1);
            __nv_bfloat162 lp = __floats2bfloat162_rn(
                v0 - __bfloat162float(hp.x), v1 - __bfloat162float(hp.y));
            *(__nv_bfloat162*)(g_at_hi + (size_t)(row0 + 8) * EMBED + col) = hp;
            *(__nv_bfloat162*)(g_at_lo + (size_t)(row0 + 8) * EMBED + col) = lp;
        }
    }
}

// ---------------------------------------------------------------------------
extern "C" void kernel_launch(void* const* d_in, const int* in_sizes, int n_in,
                              void* d_out, int out_size)
{
    const float* x     = (const float*)d_in[0];
    const float* w_qkv = (const float*)d_in[1];
    const float* b_qkv = (const float*)d_in[2];
    const float* w_o   = (const float*)d_in[3];
    const float* b_o   = (const float*)d_in[4];
    float* out = (float*)d_out;

    void *xh, *xl, *qh, *ql, *oh, *ol, *ah, *al;
    cudaGetSymbolAddress(&xh, g_x_hi);    cudaGetSymbolAddress(&xl, g_x_lo);
    cudaGetSymbolAddress(&qh, g_wqkv_hi); cudaGetSymbolAddress(&ql, g_wqkv_lo);
    cudaGetSymbolAddress(&oh, g_wo_hi);   cudaGetSymbolAddress(&ol, g_wo_lo);
    cudaGetSymbolAddress(&ah, g_at_hi);   cudaGetSymbolAddress(&al, g_at_lo);

    cudaFuncSetAttribute(tgemm<0>, cudaFuncAttributeMaxDynamicSharedMemorySize, SMEM_GEMM);
    cudaFuncSetAttribute(tgemm<1>, cudaFuncAttributeMaxDynamicSharedMemorySize, SMEM_GEMM);
    cudaFuncSetAttribute(attn_mma, cudaFuncAttributeMaxDynamicSharedMemorySize, ATT_SMEM);

    // split inputs to bf16 hi/lo
    {
        int n4 = M_ROWS * EMBED / 4;
        split_kernel<<<(n4 + 255) / 256, 256>>>(x, (__nv_bfloat16*)xh, (__nv_bfloat16*)xl, n4);
        n4 = QKV_COLS * EMBED / 4;
        split_kernel<<<(n4 + 255) / 256, 256>>>(w_qkv, (__nv_bfloat16*)qh, (__nv_bfloat16*)ql, n4);
        n4 = EMBED * EMBED / 4;
        split_kernel<<<(n4 + 255) / 256, 256>>>(w_o, (__nv_bfloat16*)oh, (__nv_bfloat16*)ol, n4);
    }

    // QKV projection -> q/k fp16 + v^T fp16
    tgemm<0><<<dim3(QKV_COLS / 128, M_ROWS / 128), 256, SMEM_GEMM>>>(
        (const __nv_bfloat16*)xh, (const __nv_bfloat16*)xl,
        (const __nv_bfloat16*)qh, (const __nv_bfloat16*)ql, b_qkv, nullptr);

    // tensor-core flash attention (fp16 internals) -> g_at hi/lo
    attn_mma<<<dim3(SEQ / 64, BATCH * NH), 128, ATT_SMEM>>>();

    // output projection -> d_out
    tgemm<1><<<dim3(EMBED / 128, M_ROWS / 128), 256, SMEM_GEMM>>>(
        (const __nv_bfloat16*)ah, (const __nv_bfloat16*)al,
        (const __nv_bfloat16*)oh, (const __nv_bfloat16*)ol, b_o, out);
}

// round 9
// speedup vs baseline: 1.9395x; 1.4411x over previous
#include <cuda_runtime.h>
#include <cuda_bf16.h>
#include <cuda_fp16.h>
#include <math.h>
#include <stdint.h>

#define EMBED 1024
#define NH 16
#define DK 64
#define BATCH 2
#define SEQ 2048
#define M_ROWS (BATCH*SEQ)      // 4096
#define QKV_COLS (3*EMBED)      // 3072

// log2(e) / sqrt(1024) — folded into Q at the QKV epilogue
#define QSCALE 0.0450842200f

// ---------------- scratch (__device__ globals) ------------------------------
__device__ __align__(16) __half g_x16[M_ROWS*EMBED];
__device__ __align__(16) __half g_wqkv16[QKV_COLS*EMBED];
__device__ __align__(16) __nv_bfloat16 g_wo_hi[EMBED*EMBED];
__device__ __align__(16) __nv_bfloat16 g_wo_lo[EMBED*EMBED];

__device__ __align__(16) __half g_qf[BATCH*NH*SEQ*DK];   // [B,H,N,dk] (pre-scaled)
__device__ __align__(16) __half g_kf[BATCH*NH*SEQ*DK];   // [B,H,N,dk]
__device__ __align__(16) __half g_vtf[BATCH*NH*DK*SEQ];  // [B,H,dk,N] (transposed)

__device__ __align__(16) __nv_bfloat16 g_at_hi[M_ROWS*EMBED];    // attention out [B,N,C]
__device__ __align__(16) __nv_bfloat16 g_at_lo[M_ROWS*EMBED];

// ---------------- PTX helpers (plain-target, sm_80-class) -------------------
__device__ __forceinline__ uint32_t smem_u32(const void* p) {
    uint32_t a;
    asm("{ .reg .u64 t; cvta.to.shared.u64 t, %1; cvt.u32.u64 %0, t; }" : "=r"(a) : "l"(p));
    return a;
}
__device__ __forceinline__ void cp16(uint32_t dst, const void* src) {
    asm volatile("cp.async.cg.shared.global [%0], [%1], 16;" :: "r"(dst), "l"(src));
}
#define CP_COMMIT() asm volatile("cp.async.commit_group;" ::: "memory")
#define CP_WAIT0()  asm volatile("cp.async.wait_group 0;" ::: "memory")
#define CP_WAIT1()  asm volatile("cp.async.wait_group 1;" ::: "memory")

__device__ __forceinline__ void ldsm_x4(uint32_t* r, uint32_t addr) {
    asm volatile("ldmatrix.sync.aligned.m8n8.x4.shared.b16 {%0,%1,%2,%3}, [%4];"
                 : "=r"(r[0]), "=r"(r[1]), "=r"(r[2]), "=r"(r[3]) : "r"(addr));
}
__device__ __forceinline__ void ldsm_x2(uint32_t* r, uint32_t addr) {
    asm volatile("ldmatrix.sync.aligned.m8n8.x2.shared.b16 {%0,%1}, [%2];"
                 : "=r"(r[0]), "=r"(r[1]) : "r"(addr));
}
__device__ __forceinline__ void mma_bf16(float* c, const uint32_t* a, const uint32_t* b) {
    asm volatile(
        "mma.sync.aligned.m16n8k16.row.col.f32.bf16.bf16.f32 "
        "{%0,%1,%2,%3}, {%4,%5,%6,%7}, {%8,%9}, {%0,%1,%2,%3};"
        : "+f"(c[0]), "+f"(c[1]), "+f"(c[2]), "+f"(c[3])
        : "r"(a[0]), "r"(a[1]), "r"(a[2]), "r"(a[3]), "r"(b[0]), "r"(b[1]));
}
__device__ __forceinline__ void mma_f16(float* c, const uint32_t* a, const uint32_t* b) {
    asm volatile(
        "mma.sync.aligned.m16n8k16.row.col.f32.f16.f16.f32 "
        "{%0,%1,%2,%3}, {%4,%5,%6,%7}, {%8,%9}, {%0,%1,%2,%3};"
        : "+f"(c[0]), "+f"(c[1]), "+f"(c[2]), "+f"(c[3])
        : "r"(a[0]), "r"(a[1]), "r"(a[2]), "r"(a[3]), "r"(b[0]), "r"(b[1]));
}
__device__ __forceinline__ float ex2(float x) {
    float y; asm("ex2.approx.f32 %0, %1;" : "=f"(y) : "f"(x)); return y;
}

// 64B-row XOR swizzle (GEMM tiles, BK=32 -> 64B rows)
__device__ __forceinline__ uint32_t sw_addr(uint32_t base, int row, int col_b16) {
    int chunk = (col_b16 >> 3) ^ ((row >> 1) & 3);
    return base + row * 64 + chunk * 16;
}
// 128B-row XOR swizzle (attention tiles, 64 fp16 = 128B rows). chunk in 16B units.
__device__ __forceinline__ uint32_t swza(uint32_t base, int row, int chunk) {
    return base + row * 128 + ((chunk ^ (row & 7)) * 16);
}

// ---------------- conversion kernels ----------------------------------------
__global__ void tohalf_kernel(const float* __restrict__ src,
                              __half* __restrict__ dst, int n4)
{
    int i = blockIdx.x * blockDim.x + threadIdx.x;
    if (i >= n4) return;
    float4 f = ((const float4*)src)[i];
    ((__half2*)dst)[2*i]   = __floats2half2_rn(f.x, f.y);
    ((__half2*)dst)[2*i+1] = __floats2half2_rn(f.z, f.w);
}

__global__ void split_kernel(const float* __restrict__ src,
                             __nv_bfloat16* __restrict__ hi,
                             __nv_bfloat16* __restrict__ lo, int n4)
{
    int i = blockIdx.x * blockDim.x + threadIdx.x;
    if (i >= n4) return;
    float4 f = ((const float4*)src)[i];
    __nv_bfloat16 h0 = __float2bfloat16(f.x), h1 = __float2bfloat16(f.y);
    __nv_bfloat16 h2 = __float2bfloat16(f.z), h3 = __float2bfloat16(f.w);
    __nv_bfloat16 l0 = __float2bfloat16(f.x - __bfloat162float(h0));
    __nv_bfloat16 l1 = __float2bfloat16(f.y - __bfloat162float(h1));
    __nv_bfloat16 l2 = __float2bfloat16(f.z - __bfloat162float(h2));
    __nv_bfloat16 l3 = __float2bfloat16(f.w - __bfloat162float(h3));
    ((__nv_bfloat162*)hi)[2*i]   = __nv_bfloat162(h0, h1);
    ((__nv_bfloat162*)hi)[2*i+1] = __nv_bfloat162(h2, h3);
    ((__nv_bfloat162*)lo)[2*i]   = __nv_bfloat162(l0, l1);
    ((__nv_bfloat162*)lo)[2*i+1] = __nv_bfloat162(l2, l3);
}

// ---------------- fp16 single-pass GEMM: QKV projection ---------------------
// C[m,n] = sum_k A[m,k]*B[n,k] + bias[n]; scatter epilogue to q/k/v^T (fp16).
// 128x128 tile, BK=32, 3-stage cp.async; 2 fp16 tiles per stage (16 KB).
#define BK 32
#define HTILE_B (128 * BK * 2)          // 8192 bytes (fp16 tile)
#define HSTAGE_B (2 * HTILE_B)          // 16384
#define SMEM_HGEMM (3 * HSTAGE_B)       // 49152

__global__ void __launch_bounds__(256)
hgemm_qkv(const __half* __restrict__ A, const __half* __restrict__ B,
          const float* __restrict__ bias)
{
    extern __shared__ char smem[];
    const uint32_t sb = smem_u32(smem);

    const int tid = threadIdx.x;
    const int bm = blockIdx.y * 128;
    const int bn = blockIdx.x * 128;

    const int tile = tid >> 7;           // 0=A 1=B
    const int slane = tid & 127;
    const __half* sbase = tile ? (B + (size_t)bn * EMBED)
                               : (A + (size_t)bm * EMBED);

    const int wid = tid >> 5;
    const int lane = tid & 31;
    const int wm = (wid >> 2) * 64;
    const int wn = (wid & 3) * 32;

    float acc[4][4][4];
#pragma unroll
    for (int i = 0; i < 4; i++)
#pragma unroll
        for (int j = 0; j < 4; j++)
#pragma unroll
            for (int t = 0; t < 4; t++) acc[i][j][t] = 0.f;

    const int NCHUNK = EMBED / BK;   // 32

    auto issue = [&](int c, int s) {
        const uint32_t tb = sb + s * HSTAGE_B + tile * HTILE_B;
        const int k0 = c * BK;
#pragma unroll
        for (int t = 0; t < 4; t++) {
            const int w = slane + t * 128;     // 0..511 16B-chunks
            const int r = w >> 2;
            const int cc = w & 3;
            cp16(sw_addr(tb, r, cc * 8), sbase + (size_t)r * EMBED + k0 + cc * 8);
        }
        CP_COMMIT();
    };

    issue(0, 0);
    issue(1, 1);

    int s = 0;
    for (int c = 0; c < NCHUNK; c++) {
        CP_WAIT1();
        __syncthreads();
        if (c + 2 < NCHUNK) issue(c + 2, (c + 2) % 3);

        const uint32_t sA = sb + s * HSTAGE_B;
        const uint32_t sB = sA + HTILE_B;

#pragma unroll
        for (int ks = 0; ks < 2; ks++) {
            uint32_t af[4][4], bf[4][2];
            const int arow = wm + (lane & 15);
            const int acol = ks * 16 + (lane >> 4) * 8;
            const int brow = wn + (lane & 7);
            const int bcol = ks * 16 + ((lane >> 3) & 1) * 8;
#pragma unroll
            for (int mt = 0; mt < 4; mt++)
                ldsm_x4(af[mt], sw_addr(sA, arow + mt * 16, acol));
#pragma unroll
            for (int nt = 0; nt < 4; nt++)
                ldsm_x2(bf[nt], sw_addr(sB, brow + nt * 8, bcol));
#pragma unroll
            for (int mt = 0; mt < 4; mt++)
#pragma unroll
                for (int nt = 0; nt < 4; nt++)
                    mma_f16(acc[mt][nt], af[mt], bf[nt]);
        }
        s = (s + 1 == 3) ? 0 : s + 1;
    }

#pragma unroll
    for (int mt = 0; mt < 4; mt++) {
#pragma unroll
        for (int half = 0; half < 2; half++) {
            const int m = bm + wm + mt * 16 + (lane >> 2) + half * 8;
            const int bi = m >> 11;
            const int tt = m & 2047;
#pragma unroll
            for (int nt = 0; nt < 4; nt++) {
                const int n0 = bn + wn + nt * 8 + (lane & 3) * 2;
                float v0 = acc[mt][nt][half * 2 + 0] + bias[n0];
                float v1 = acc[mt][nt][half * 2 + 1] + bias[n0 + 1];
                const int which = n0 >> 10;
                const int cc = n0 & 1023;
                const int h = cc >> 6;
                const int d = cc & 63;
                const int bh = bi * NH + h;
                if (which == 0) { v0 *= QSCALE; v1 *= QSCALE; }
                if (which < 2) {
                    __half* dst = which ? g_kf : g_qf;
                    const size_t idx = ((size_t)bh * SEQ + tt) * DK + d;
                    *(__half2*)(dst + idx) = __floats2half2_rn(v0, v1);
                } else {
                    const size_t idx = ((size_t)bh * DK + d) * SEQ + tt;
                    g_vtf[idx]       = __float2half_rn(v0);
                    g_vtf[idx + SEQ] = __float2half_rn(v1);
                }
            }
        }
    }
}

// ---------------- mma.sync split-bf16 GEMM (out-proj, 3-stage) --------------
#define TILE_B (128 * BK * 2)          // 8192 bytes
#define STAGE_B (4 * TILE_B)           // 32768
#define SMEM_GEMM (3 * STAGE_B)        // 98304

__global__ void __launch_bounds__(256)
tgemm_out(const __nv_bfloat16* __restrict__ Ahi, const __nv_bfloat16* __restrict__ Alo,
          const __nv_bfloat16* __restrict__ Bhi, const __nv_bfloat16* __restrict__ Blo,
          const float* __restrict__ bias, float* __restrict__ Cout)
{
    extern __shared__ char smem[];
    const uint32_t sb = smem_u32(smem);

    const int tid = threadIdx.x;
    const int bm = blockIdx.y * 128;
    const int bn = blockIdx.x * 128;

    const int tile = tid >> 6;
    const int slane = tid & 63;
    const __nv_bfloat16* sbase;
    if      (tile == 0) sbase = Ahi + (size_t)bm * EMBED;
    else if (tile == 1) sbase = Alo + (size_t)bm * EMBED;
    else if (tile == 2) sbase = Bhi + (size_t)bn * EMBED;
    else                sbase = Blo + (size_t)bn * EMBED;

    const int wid = tid >> 5;
    const int lane = tid & 31;
    const int wm = (wid >> 2) * 64;
    const int wn = (wid & 3) * 32;

    float acc[4][4][4];
#pragma unroll
    for (int i = 0; i < 4; i++)
#pragma unroll
        for (int j = 0; j < 4; j++)
#pragma unroll
            for (int t = 0; t < 4; t++) acc[i][j][t] = 0.f;

    const int NCHUNK = EMBED / BK;   // 32

    auto issue = [&](int c, int s) {
        const uint32_t tb = sb + s * STAGE_B + tile * TILE_B;
        const int k0 = c * BK;
#pragma unroll
        for (int t = 0; t < 8; t++) {
            const int w = slane + t * 64;
            const int r = w >> 2;
            const int cc = w & 3;
            cp16(sw_addr(tb, r, cc * 8), sbase + (size_t)r * EMBED + k0 + cc * 8);
        }
        CP_COMMIT();
    };

    issue(0, 0);
    issue(1, 1);

    int s = 0;
    for (int c = 0; c < NCHUNK; c++) {
        CP_WAIT1();
        __syncthreads();
        if (c + 2 < NCHUNK) issue(c + 2, (c + 2) % 3);

        const uint32_t sAhi = sb + s * STAGE_B;
        const uint32_t sAlo = sAhi + TILE_B;
        const uint32_t sBhi = sAhi + 2 * TILE_B;
        const uint32_t sBlo = sAhi + 3 * TILE_B;

#pragma unroll
        for (int ks = 0; ks < 2; ks++) {
            uint32_t ah[4][4], al[4][4], bh[4][2], bl[4][2];
            const int arow = wm + (lane & 15);
            const int acol = ks * 16 + (lane >> 4) * 8;
            const int brow = wn + (lane & 7);
            const int bcol = ks * 16 + ((lane >> 3) & 1) * 8;
#pragma unroll
            for (int mt = 0; mt < 4; mt++) {
                ldsm_x4(ah[mt], sw_addr(sAhi, arow + mt * 16, acol));
                ldsm_x4(al[mt], sw_addr(sAlo, arow + mt * 16, acol));
            }
#pragma unroll
            for (int nt = 0; nt < 4; nt++) {
                ldsm_x2(bh[nt], sw_addr(sBhi, brow + nt * 8, bcol));
                ldsm_x2(bl[nt], sw_addr(sBlo, brow + nt * 8, bcol));
            }
#pragma unroll
            for (int mt = 0; mt < 4; mt++)
#pragma unroll
                for (int nt = 0; nt < 4; nt++) {
                    mma_bf16(acc[mt][nt], ah[mt], bh[nt]);
                    mma_bf16(acc[mt][nt], ah[mt], bl[nt]);
                    mma_bf16(acc[mt][nt], al[mt], bh[nt]);
                }
        }
        s = (s + 1 == 3) ? 0 : s + 1;
    }

#pragma unroll
    for (int mt = 0; mt < 4; mt++) {
#pragma unroll
        for (int half = 0; half < 2; half++) {
            const int m = bm + wm + mt * 16 + (lane >> 2) + half * 8;
#pragma unroll
            for (int nt = 0; nt < 4; nt++) {
                const int n0 = bn + wn + nt * 8 + (lane & 3) * 2;
                Cout[(size_t)m * EMBED + n0]     = acc[mt][nt][half * 2 + 0] + bias[n0];
                Cout[(size_t)m * EMBED + n0 + 1] = acc[mt][nt][half * 2 + 1] + bias[n0 + 1];
            }
        }
    }
}

// ---------------- tensor-core causal flash attention (fp16, single-pass) ----
// CTA: 64 queries (4 warps x 16 rows), key tiles of 64, 2-stage cp.async.
#define ATT_SMEM (8192 + 2 * 16384)

__global__ void __launch_bounds__(128) attn_mma()
{
    extern __shared__ char smem[];
    const uint32_t sb = smem_u32(smem);
    const uint32_t q_s = sb;
    const uint32_t stage0 = sb + 8192;

    const int tid = threadIdx.x;
    const int lane = tid & 31;
    const int wid = tid >> 5;
    const int g = lane >> 2;
    const int tg = lane & 3;
    const int bh = blockIdx.y;
    const int qb = (int)(gridDim.x - 1 - blockIdx.x);   // heavy blocks first

    const __half* q_g  = g_qf  + ((size_t)bh * SEQ + qb * 64) * DK;
    const __half* k_g  = g_kf  + (size_t)bh * SEQ * DK;
    const __half* vt_g = g_vtf + (size_t)bh * DK * SEQ;

#pragma unroll
    for (int i = 0; i < 4; i++) {
        const int w = tid + i * 128;
        const int r = w >> 3, c = w & 7;
        cp16(swza(q_s, r, c), q_g + (size_t)r * DK + c * 8);
    }
    CP_COMMIT();

    auto issue_tile = [&](int kt, int s) {
        const uint32_t st = stage0 + s * 16384;
        const int k0 = kt * 64;
#pragma unroll
        for (int i = 0; i < 4; i++) {
            const int w = tid + i * 128;
            const int r = w >> 3, c = w & 7;
            const uint32_t off = r * 128 + ((c ^ (r & 7)) * 16);
            cp16(st + off,        k_g + (size_t)(k0 + r) * DK + c * 8);
            cp16(st + 8192 + off, vt_g + (size_t)r * SEQ + k0 + c * 8);
        }
        CP_COMMIT();
    };

    issue_tile(0, 0);

    uint32_t qf[4][4];
    float oacc[8][4];
#pragma unroll
    for (int nt = 0; nt < 8; nt++)
#pragma unroll
        for (int t = 0; t < 4; t++) oacc[nt][t] = 0.f;
    float m0 = -1e30f, m1 = -1e30f, l0 = 0.f, l1 = 0.f;

    for (int kt = 0; kt <= qb; kt++) {
        const int s = kt & 1;
        if (kt < qb) { issue_tile(kt + 1, s ^ 1); CP_WAIT1(); }
        else         { CP_WAIT0(); }
        __syncthreads();

        if (kt == 0) {
            const int arow = wid * 16 + (lane & 15);
            const int ach = lane >> 4;
#pragma unroll
            for (int kc = 0; kc < 4; kc++)
                ldsm_x4(qf[kc], swza(q_s, arow, kc * 2 + ach));
        }

        const uint32_t sK  = stage0 + s * 16384;
        const uint32_t sVT = sK + 8192;
        const int br = lane & 7;
        const int bc = (lane >> 3) & 1;

        float sacc[8][4];
#pragma unroll
        for (int nt = 0; nt < 8; nt++)
#pragma unroll
            for (int t = 0; t < 4; t++) sacc[nt][t] = 0.f;

#pragma unroll
        for (int kc = 0; kc < 4; kc++) {
            uint32_t bf[8][2];
#pragma unroll
            for (int nt = 0; nt < 8; nt++)
                ldsm_x2(bf[nt], swza(sK, nt * 8 + br, kc * 2 + bc));
#pragma unroll
            for (int nt = 0; nt < 8; nt++)
                mma_f16(sacc[nt], qf[kc], bf[nt]);
        }

        if (kt == qb) {
#pragma unroll
            for (int nt = 0; nt < 8; nt++)
#pragma unroll
                for (int idx = 0; idx < 4; idx++) {
                    const int key = nt * 8 + tg * 2 + (idx & 1);
                    const int qr  = wid * 16 + g + (idx >> 1) * 8;
                    if (key > qr) sacc[nt][idx] = -1e30f;
                }
        }

        float mx0 = -1e30f, mx1 = -1e30f;
#pragma unroll
        for (int nt = 0; nt < 8; nt++) {
            mx0 = fmaxf(mx0, fmaxf(sacc[nt][0], sacc[nt][1]));
            mx1 = fmaxf(mx1, fmaxf(sacc[nt][2], sacc[nt][3]));
        }
        mx0 = fmaxf(mx0, __shfl_xor_sync(0xffffffffu, mx0, 1));
        mx0 = fmaxf(mx0, __shfl_xor_sync(0xffffffffu, mx0, 2));
        mx1 = fmaxf(mx1, __shfl_xor_sync(0xffffffffu, mx1, 1));
        mx1 = fmaxf(mx1, __shfl_xor_sync(0xffffffffu, mx1, 2));

        const float mn0 = fmaxf(m0, mx0);
        const float mn1 = fmaxf(m1, mx1);
        const float a0 = ex2(m0 - mn0);
        const float a1 = ex2(m1 - mn1);
        m0 = mn0; m1 = mn1;
        l0 *= a0; l1 *= a1;
#pragma unroll
        for (int nt = 0; nt < 8; nt++) {
            oacc[nt][0] *= a0; oacc[nt][1] *= a0;
            oacc[nt][2] *= a1; oacc[nt][3] *= a1;
        }

        uint32_t pf[4][4];
        float ps0 = 0.f, ps1 = 0.f;
#pragma unroll
        for (int nt = 0; nt < 8; nt++) {
            const float p0 = ex2(sacc[nt][0] - mn0);
            const float p1 = ex2(sacc[nt][1] - mn0);
            const float p2 = ex2(sacc[nt][2] - mn1);
            const float p3 = ex2(sacc[nt][3] - mn1);
            ps0 += p0 + p1; ps1 += p2 + p3;
            const int kc = nt >> 1;
            const int r = (nt & 1) * 2;
            __half2 hp01 = __floats2half2_rn(p0, p1);
            __half2 hp23 = __floats2half2_rn(p2, p3);
            pf[kc][r + 0] = *(uint32_t*)&hp01;
            pf[kc][r + 1] = *(uint32_t*)&hp23;
        }
        ps0 += __shfl_xor_sync(0xffffffffu, ps0, 1);
        ps0 += __shfl_xor_sync(0xffffffffu, ps0, 2);
        ps1 += __shfl_xor_sync(0xffffffffu, ps1, 1);
        ps1 += __shfl_xor_sync(0xffffffffu, ps1, 2);
        l0 += ps0; l1 += ps1;

#pragma unroll
        for (int kc = 0; kc < 4; kc++) {
            uint32_t vf[8][2];
#pragma unroll
            for (int nt = 0; nt < 8; nt++)
                ldsm_x2(vf[nt], swza(sVT, nt * 8 + br, kc * 2 + bc));
#pragma unroll
            for (int nt = 0; nt < 8; nt++)
                mma_f16(oacc[nt], pf[kc], vf[nt]);
        }
        __syncthreads();
    }

    const float inv0 = 1.0f / l0;
    const float inv1 = 1.0f / l1;
    const int bi = bh >> 4;
    const int h  = bh & 15;
    const int row0 = bi * SEQ + qb * 64 + wid * 16 + g;
#pragma unroll
    for (int nt = 0; nt < 8; nt++) {
        const int col = h * 64 + nt * 8 + tg * 2;
        {
            const float v0 = oacc[nt][0] * inv0, v1 = oacc[nt][1] * inv0;
            __nv_bfloat162 hp = __floats2bfloat162_rn(v0, v1);
            __nv_bfloat162 lp = __floats2bfloat162_rn(
                v0 - __bfloat162float(hp.x), v1 - __bfloat162float(hp.y));
            *(__nv_bfloat162*)(g_at_hi + (size_t)row0 * EMBED + col) = hp;
            *(__nv_bfloat162*)(g_at_lo + (size_t)row0 * EMBED + col) = lp;
        }
        {
            const float v0 = oacc[nt][2] * inv1, v1 = oacc[nt][3] * inv1;
            __nv_bfloat162 hp = __floats2bfloat162_rn(v0, v1);
            __nv_bfloat162 lp = __floats2bfloat162_rn(
                v0 - __bfloat162float(hp.x), v1 - __bfloat162float(hp.y));
            *(__nv_bfloat162*)(g_at_hi + (size_t)(row0 + 8) * EMBED + col) = hp;
            *(__nv_bfloat162*)(g_at_lo + (size_t)(row0 + 8) * EMBED + col) = lp;
        }
    }
}

// ---------------------------------------------------------------------------
extern "C" void kernel_launch(void* const* d_in, const int* in_sizes, int n_in,
                              void* d_out, int out_size)
{
    const float* x     = (const float*)d_in[0];
    const float* w_qkv = (const float*)d_in[1];
    const float* b_qkv = (const float*)d_in[2];
    const float* w_o   = (const float*)d_in[3];
    const float* b_o   = (const float*)d_in[4];
    float* out = (float*)d_out;

    void *x16, *wq16, *oh, *ol, *ah, *al;
    cudaGetSymbolAddress(&x16, g_x16);
    cudaGetSymbolAddress(&wq16, g_wqkv16);
    cudaGetSymbolAddress(&oh, g_wo_hi);   cudaGetSymbolAddress(&ol, g_wo_lo);
    cudaGetSymbolAddress(&ah, g_at_hi);   cudaGetSymbolAddress(&al, g_at_lo);

    cudaFuncSetAttribute(hgemm_qkv, cudaFuncAttributeMaxDynamicSharedMemorySize, SMEM_HGEMM);
    cudaFuncSetAttribute(tgemm_out, cudaFuncAttributeMaxDynamicSharedMemorySize, SMEM_GEMM);
    cudaFuncSetAttribute(attn_mma, cudaFuncAttributeMaxDynamicSharedMemorySize, ATT_SMEM);

    // conversions
    {
        int n4 = M_ROWS * EMBED / 4;
        tohalf_kernel<<<(n4 + 255) / 256, 256>>>(x, (__half*)x16, n4);
        n4 = QKV_COLS * EMBED / 4;
        tohalf_kernel<<<(n4 + 255) / 256, 256>>>(w_qkv, (__half*)wq16, n4);
        n4 = EMBED * EMBED / 4;
        split_kernel<<<(n4 + 255) / 256, 256>>>(w_o, (__nv_bfloat16*)oh, (__nv_bfloat16*)ol, n4);
    }

    // QKV projection (fp16 single-pass) -> q/k fp16 + v^T fp16
    hgemm_qkv<<<dim3(QKV_COLS / 128, M_ROWS / 128), 256, SMEM_HGEMM>>>(
        (const __half*)x16, (const __half*)wq16, b_qkv);

    // tensor-core flash attention (fp16 internals) -> g_at hi/lo
    attn_mma<<<dim3(SEQ / 64, BATCH * NH), 128, ATT_SMEM>>>();

    // output projection (bf16 3-pass, keeps error margin) -> d_out
    tgemm_out<<<dim3(EMBED / 128, M_ROWS / 128), 256, SMEM_GEMM>>>(
        (const __nv_bfloat16*)ah, (const __nv_bfloat16*)al,
        (const __nv_bfloat16*)oh, (const __nv_bfloat16*)ol, b_o, out);
}

// round 10
// speedup vs baseline: 2.5833x; 1.3320x over previous
#include <cuda_runtime.h>
#include <cuda_bf16.h>
#include <cuda_fp16.h>
#include <math.h>
#include <stdint.h>

#define EMBED 1024
#define NH 16
#define DK 64
#define BATCH 2
#define SEQ 2048
#define M_ROWS (BATCH*SEQ)      // 4096
#define QKV_COLS (3*EMBED)      // 3072

// log2(e) / sqrt(1024) — folded into Q at the QKV epilogue
#define QSCALE 0.0450842200f

// ---------------- scratch (__device__ globals) ------------------------------
__device__ __align__(16) __half g_x16[M_ROWS*EMBED];
__device__ __align__(16) __half g_wqkv16[QKV_COLS*EMBED];
__device__ __align__(16) __half g_wo16[EMBED*EMBED];

__device__ __align__(16) __half g_qf[BATCH*NH*SEQ*DK];   // [B,H,N,dk] (pre-scaled)
__device__ __align__(16) __half g_kf[BATCH*NH*SEQ*DK];   // [B,H,N,dk]
__device__ __align__(16) __half g_vtf[BATCH*NH*DK*SEQ];  // [B,H,dk,N] (transposed)

__device__ __align__(16) __half g_atf[M_ROWS*EMBED];     // attention out [B,N,C]

// ---------------- PTX helpers (plain-target, sm_80-class) -------------------
__device__ __forceinline__ uint32_t smem_u32(const void* p) {
    uint32_t a;
    asm("{ .reg .u64 t; cvta.to.shared.u64 t, %1; cvt.u32.u64 %0, t; }" : "=r"(a) : "l"(p));
    return a;
}
__device__ __forceinline__ void cp16(uint32_t dst, const void* src) {
    asm volatile("cp.async.cg.shared.global [%0], [%1], 16;" :: "r"(dst), "l"(src));
}
#define CP_COMMIT() asm volatile("cp.async.commit_group;" ::: "memory")
#define CP_WAIT0()  asm volatile("cp.async.wait_group 0;" ::: "memory")
#define CP_WAIT1()  asm volatile("cp.async.wait_group 1;" ::: "memory")

__device__ __forceinline__ void ldsm_x4(uint32_t* r, uint32_t addr) {
    asm volatile("ldmatrix.sync.aligned.m8n8.x4.shared.b16 {%0,%1,%2,%3}, [%4];"
                 : "=r"(r[0]), "=r"(r[1]), "=r"(r[2]), "=r"(r[3]) : "r"(addr));
}
__device__ __forceinline__ void ldsm_x2(uint32_t* r, uint32_t addr) {
    asm volatile("ldmatrix.sync.aligned.m8n8.x2.shared.b16 {%0,%1}, [%2];"
                 : "=r"(r[0]), "=r"(r[1]) : "r"(addr));
}
__device__ __forceinline__ void mma_f16(float* c, const uint32_t* a, const uint32_t* b) {
    asm volatile(
        "mma.sync.aligned.m16n8k16.row.col.f32.f16.f16.f32 "
        "{%0,%1,%2,%3}, {%4,%5,%6,%7}, {%8,%9}, {%0,%1,%2,%3};"
        : "+f"(c[0]), "+f"(c[1]), "+f"(c[2]), "+f"(c[3])
        : "r"(a[0]), "r"(a[1]), "r"(a[2]), "r"(a[3]), "r"(b[0]), "r"(b[1]));
}
__device__ __forceinline__ float ex2(float x) {
    float y; asm("ex2.approx.f32 %0, %1;" : "=f"(y) : "f"(x)); return y;
}

// 128B-row XOR swizzle (rows of 64 fp16 = 128B). chunk in 16B units (0..7).
__device__ __forceinline__ uint32_t swza(uint32_t base, int row, int chunk) {
    return base + row * 128 + ((chunk ^ (row & 7)) * 16);
}

// ---------------- conversion kernel -----------------------------------------
__global__ void tohalf_kernel(const float* __restrict__ src,
                              __half* __restrict__ dst, int n4)
{
    int i = blockIdx.x * blockDim.x + threadIdx.x;
    if (i >= n4) return;
    float4 f = ((const float4*)src)[i];
    ((__half2*)dst)[2*i]   = __floats2half2_rn(f.x, f.y);
    ((__half2*)dst)[2*i+1] = __floats2half2_rn(f.z, f.w);
}

// ---------------- fp16 single-pass GEMM (BK=64, 3-stage) --------------------
// C[m,n] = sum_k A[m,k]*B[n,k] + bias[n]
// EPI=0: QKV scatter -> q/k fp16 (q pre-scaled) + v^T fp16
// EPI=1: out-proj -> fp32 Cout
#define BK 64
#define HTILE_B (128 * BK * 2)          // 16384 bytes (fp16 tile, 128B rows)
#define HSTAGE_B (2 * HTILE_B)          // 32768
#define SMEM_HGEMM (3 * HSTAGE_B)       // 98304

template<int EPI>
__global__ void __launch_bounds__(256)
hgemm(const __half* __restrict__ A, const __half* __restrict__ B,
      const float* __restrict__ bias, float* __restrict__ Cout)
{
    extern __shared__ char smem[];
    const uint32_t sb = smem_u32(smem);

    const int tid = threadIdx.x;
    const int bm = blockIdx.y * 128;
    const int bn = blockIdx.x * 128;

    const int tile = tid >> 7;           // 0=A 1=B
    const int slane = tid & 127;
    const __half* sbase = tile ? (B + (size_t)bn * EMBED)
                               : (A + (size_t)bm * EMBED);

    const int wid = tid >> 5;
    const int lane = tid & 31;
    const int wm = (wid >> 2) * 64;
    const int wn = (wid & 3) * 32;

    float acc[4][4][4];
#pragma unroll
    for (int i = 0; i < 4; i++)
#pragma unroll
        for (int j = 0; j < 4; j++)
#pragma unroll
            for (int t = 0; t < 4; t++) acc[i][j][t] = 0.f;

    const int NCHUNK = EMBED / BK;   // 16

    auto issue = [&](int c, int s) {
        const uint32_t tb = sb + s * HSTAGE_B + tile * HTILE_B;
        const int k0 = c * BK;
#pragma unroll
        for (int t = 0; t < 8; t++) {
            const int w = slane + t * 128;     // 0..1023 16B-chunks per tile
            const int r = w >> 3;              // row 0..127
            const int cc = w & 7;              // chunk 0..7
            cp16(swza(tb, r, cc), sbase + (size_t)r * EMBED + k0 + cc * 8);
        }
        CP_COMMIT();
    };

    issue(0, 0);
    issue(1, 1);

    int s = 0;
    for (int c = 0; c < NCHUNK; c++) {
        CP_WAIT1();
        __syncthreads();
        if (c + 2 < NCHUNK) issue(c + 2, (c + 2) % 3);

        const uint32_t sA = sb + s * HSTAGE_B;
        const uint32_t sB = sA + HTILE_B;
        const int ach = lane >> 4;             // 0/1
        const int bch = (lane >> 3) & 1;       // 0/1
        const int arow = wm + (lane & 15);
        const int brow0 = wn + (lane & 7);

#pragma unroll
        for (int ks = 0; ks < 4; ks++) {       // 4 k-steps of 16 within BK=64
            uint32_t af[4][4], bf[4][2];
#pragma unroll
            for (int mt = 0; mt < 4; mt++)
                ldsm_x4(af[mt], swza(sA, arow + mt * 16, ks * 2 + ach));
#pragma unroll
            for (int nt = 0; nt < 4; nt++)
                ldsm_x2(bf[nt], swza(sB, brow0 + nt * 8, ks * 2 + bch));
#pragma unroll
            for (int mt = 0; mt < 4; mt++)
#pragma unroll
                for (int nt = 0; nt < 4; nt++)
                    mma_f16(acc[mt][nt], af[mt], bf[nt]);
        }
        s = (s + 1 == 3) ? 0 : s + 1;
    }

#pragma unroll
    for (int mt = 0; mt < 4; mt++) {
#pragma unroll
        for (int half = 0; half < 2; half++) {
            const int m = bm + wm + mt * 16 + (lane >> 2) + half * 8;
            const int bi = m >> 11;
            const int tt = m & 2047;
#pragma unroll
            for (int nt = 0; nt < 4; nt++) {
                const int n0 = bn + wn + nt * 8 + (lane & 3) * 2;
                float v0 = acc[mt][nt][half * 2 + 0] + bias[n0];
                float v1 = acc[mt][nt][half * 2 + 1] + bias[n0 + 1];
                if (EPI == 0) {
                    const int which = n0 >> 10;
                    const int cc = n0 & 1023;
                    const int h = cc >> 6;
                    const int d = cc & 63;
                    const int bh = bi * NH + h;
                    if (which == 0) { v0 *= QSCALE; v1 *= QSCALE; }
                    if (which < 2) {
                        __half* dst = which ? g_kf : g_qf;
                        const size_t idx = ((size_t)bh * SEQ + tt) * DK + d;
                        *(__half2*)(dst + idx) = __floats2half2_rn(v0, v1);
                    } else {
                        const size_t idx = ((size_t)bh * DK + d) * SEQ + tt;
                        g_vtf[idx]       = __float2half_rn(v0);
                        g_vtf[idx + SEQ] = __float2half_rn(v1);
                    }
                } else {
                    Cout[(size_t)m * EMBED + n0]     = v0;
                    Cout[(size_t)m * EMBED + n0 + 1] = v1;
                }
            }
        }
    }
}

// ---------------- tensor-core causal flash attention (fp16, single-pass) ----
// CTA: 64 queries (4 warps x 16 rows), key tiles of 64, 2-stage cp.async.
#define ATT_SMEM (8192 + 2 * 16384)

__global__ void __launch_bounds__(128) attn_mma()
{
    extern __shared__ char smem[];
    const uint32_t sb = smem_u32(smem);
    const uint32_t q_s = sb;
    const uint32_t stage0 = sb + 8192;

    const int tid = threadIdx.x;
    const int lane = tid & 31;
    const int wid = tid >> 5;
    const int g = lane >> 2;
    const int tg = lane & 3;
    const int bh = blockIdx.y;
    const int qb = (int)(gridDim.x - 1 - blockIdx.x);   // heavy blocks first

    const __half* q_g  = g_qf  + ((size_t)bh * SEQ + qb * 64) * DK;
    const __half* k_g  = g_kf  + (size_t)bh * SEQ * DK;
    const __half* vt_g = g_vtf + (size_t)bh * DK * SEQ;

#pragma unroll
    for (int i = 0; i < 4; i++) {
        const int w = tid + i * 128;
        const int r = w >> 3, c = w & 7;
        cp16(swza(q_s, r, c), q_g + (size_t)r * DK + c * 8);
    }
    CP_COMMIT();

    auto issue_tile = [&](int kt, int s) {
        const uint32_t st = stage0 + s * 16384;
        const int k0 = kt * 64;
#pragma unroll
        for (int i = 0; i < 4; i++) {
            const int w = tid + i * 128;
            const int r = w >> 3, c = w & 7;
            cp16(swza(st, r, c),        k_g + (size_t)(k0 + r) * DK + c * 8);
            cp16(swza(st + 8192, r, c), vt_g + (size_t)r * SEQ + k0 + c * 8);
        }
        CP_COMMIT();
    };

    issue_tile(0, 0);

    uint32_t qf[4][4];
    float oacc[8][4];
#pragma unroll
    for (int nt = 0; nt < 8; nt++)
#pragma unroll
        for (int t = 0; t < 4; t++) oacc[nt][t] = 0.f;
    float m0 = -1e30f, m1 = -1e30f, l0 = 0.f, l1 = 0.f;

    for (int kt = 0; kt <= qb; kt++) {
        const int s = kt & 1;
        if (kt < qb) { issue_tile(kt + 1, s ^ 1); CP_WAIT1(); }
        else         { CP_WAIT0(); }
        __syncthreads();

        if (kt == 0) {
            const int arow = wid * 16 + (lane & 15);
            const int ach = lane >> 4;
#pragma unroll
            for (int kc = 0; kc < 4; kc++)
                ldsm_x4(qf[kc], swza(q_s, arow, kc * 2 + ach));
        }

        const uint32_t sK  = stage0 + s * 16384;
        const uint32_t sVT = sK + 8192;
        const int br = lane & 7;
        const int bc = (lane >> 3) & 1;

        float sacc[8][4];
#pragma unroll
        for (int nt = 0; nt < 8; nt++)
#pragma unroll
            for (int t = 0; t < 4; t++) sacc[nt][t] = 0.f;

#pragma unroll
        for (int kc = 0; kc < 4; kc++) {
            uint32_t bf[8][2];
#pragma unroll
            for (int nt = 0; nt < 8; nt++)
                ldsm_x2(bf[nt], swza(sK, nt * 8 + br, kc * 2 + bc));
#pragma unroll
            for (int nt = 0; nt < 8; nt++)
                mma_f16(sacc[nt], qf[kc], bf[nt]);
        }

        if (kt == qb) {
#pragma unroll
            for (int nt = 0; nt < 8; nt++)
#pragma unroll
                for (int idx = 0; idx < 4; idx++) {
                    const int key = nt * 8 + tg * 2 + (idx & 1);
                    const int qr  = wid * 16 + g + (idx >> 1) * 8;
                    if (key > qr) sacc[nt][idx] = -1e30f;
                }
        }

        float mx0 = -1e30f, mx1 = -1e30f;
#pragma unroll
        for (int nt = 0; nt < 8; nt++) {
            mx0 = fmaxf(mx0, fmaxf(sacc[nt][0], sacc[nt][1]));
            mx1 = fmaxf(mx1, fmaxf(sacc[nt][2], sacc[nt][3]));
        }
        mx0 = fmaxf(mx0, __shfl_xor_sync(0xffffffffu, mx0, 1));
        mx0 = fmaxf(mx0, __shfl_xor_sync(0xffffffffu, mx0, 2));
        mx1 = fmaxf(mx1, __shfl_xor_sync(0xffffffffu, mx1, 1));
        mx1 = fmaxf(mx1, __shfl_xor_sync(0xffffffffu, mx1, 2));

        const float mn0 = fmaxf(m0, mx0);
        const float mn1 = fmaxf(m1, mx1);
        const float a0 = ex2(m0 - mn0);
        const float a1 = ex2(m1 - mn1);
        m0 = mn0; m1 = mn1;
        l0 *= a0; l1 *= a1;
#pragma unroll
        for (int nt = 0; nt < 8; nt++) {
            oacc[nt][0] *= a0; oacc[nt][1] *= a0;
            oacc[nt][2] *= a1; oacc[nt][3] *= a1;
        }

        uint32_t pf[4][4];
        float ps0 = 0.f, ps1 = 0.f;
#pragma unroll
        for (int nt = 0; nt < 8; nt++) {
            const float p0 = ex2(sacc[nt][0] - mn0);
            const float p1 = ex2(sacc[nt][1] - mn0);
            const float p2 = ex2(sacc[nt][2] - mn1);
            const float p3 = ex2(sacc[nt][3] - mn1);
            ps0 += p0 + p1; ps1 += p2 + p3;
            const int kc = nt >> 1;
            const int r = (nt & 1) * 2;
            __half2 hp01 = __floats2half2_rn(p0, p1);
            __half2 hp23 = __floats2half2_rn(p2, p3);
            pf[kc][r + 0] = *(uint32_t*)&hp01;
            pf[kc][r + 1] = *(uint32_t*)&hp23;
        }
        ps0 += __shfl_xor_sync(0xffffffffu, ps0, 1);
        ps0 += __shfl_xor_sync(0xffffffffu, ps0, 2);
        ps1 += __shfl_xor_sync(0xffffffffu, ps1, 1);
        ps1 += __shfl_xor_sync(0xffffffffu, ps1, 2);
        l0 += ps0; l1 += ps1;

#pragma unroll
        for (int kc = 0; kc < 4; kc++) {
            uint32_t vf[8][2];
#pragma unroll
            for (int nt = 0; nt < 8; nt++)
                ldsm_x2(vf[nt], swza(sVT, nt * 8 + br, kc * 2 + bc));
#pragma unroll
            for (int nt = 0; nt < 8; nt++)
                mma_f16(oacc[nt], pf[kc], vf[nt]);
        }
        __syncthreads();
    }

    // ---- normalize + write fp16 [B,N,C] ----
    const float inv0 = 1.0f / l0;
    const float inv1 = 1.0f / l1;
    const int bi = bh >> 4;
    const int h  = bh & 15;
    const int row0 = bi * SEQ + qb * 64 + wid * 16 + g;
#pragma unroll
    for (int nt = 0; nt < 8; nt++) {
        const int col = h * 64 + nt * 8 + tg * 2;
        *(__half2*)(g_atf + (size_t)row0 * EMBED + col) =
            __floats2half2_rn(oacc[nt][0] * inv0, oacc[nt][1] * inv0);
        *(__half2*)(g_atf + (size_t)(row0 + 8) * EMBED + col) =
            __floats2half2_rn(oacc[nt][2] * inv1, oacc[nt][3] * inv1);
    }
}

// ---------------------------------------------------------------------------
extern "C" void kernel_launch(void* const* d_in, const int* in_sizes, int n_in,
                              void* d_out, int out_size)
{
    const float* x     = (const float*)d_in[0];
    const float* w_qkv = (const float*)d_in[1];
    const float* b_qkv = (const float*)d_in[2];
    const float* w_o   = (const float*)d_in[3];
    const float* b_o   = (const float*)d_in[4];
    float* out = (float*)d_out;

    void *x16, *wq16, *wo16, *at16;
    cudaGetSymbolAddress(&x16, g_x16);
    cudaGetSymbolAddress(&wq16, g_wqkv16);
    cudaGetSymbolAddress(&wo16, g_wo16);
    cudaGetSymbolAddress(&at16, g_atf);

    cudaFuncSetAttribute(hgemm<0>, cudaFuncAttributeMaxDynamicSharedMemorySize, SMEM_HGEMM);
    cudaFuncSetAttribute(hgemm<1>, cudaFuncAttributeMaxDynamicSharedMemorySize, SMEM_HGEMM);
    cudaFuncSetAttribute(attn_mma, cudaFuncAttributeMaxDynamicSharedMemorySize, ATT_SMEM);

    // fp32 -> fp16 conversions
    {
        int n4 = M_ROWS * EMBED / 4;
        tohalf_kernel<<<(n4 + 255) / 256, 256>>>(x, (__half*)x16, n4);
        n4 = QKV_COLS * EMBED / 4;
        tohalf_kernel<<<(n4 + 255) / 256, 256>>>(w_qkv, (__half*)wq16, n4);
        n4 = EMBED * EMBED / 4;
        tohalf_kernel<<<(n4 + 255) / 256, 256>>>(w_o, (__half*)wo16, n4);
    }

    // QKV projection (fp16, BK=64) -> q/k fp16 + v^T fp16
    hgemm<0><<<dim3(QKV_COLS / 128, M_ROWS / 128), 256, SMEM_HGEMM>>>(
        (const __half*)x16, (const __half*)wq16, b_qkv, nullptr);

    // tensor-core flash attention (fp16) -> g_atf
    attn_mma<<<dim3(SEQ / 64, BATCH * NH), 128, ATT_SMEM>>>();

    // output projection (fp16, BK=64) -> d_out
    hgemm<1><<<dim3(EMBED / 128, M_ROWS / 128), 256, SMEM_HGEMM>>>(
        (const __half*)at16, (const __half*)wo16, b_o, out);
}